// round 5
// baseline (speedup 1.0000x reference)
#include <cuda_runtime.h>
#include <cuda_bf16.h>
#include <math.h>
#include <stdint.h>

// Shapes (fixed)
#define BB 32
#define TT 512
#define AA 64
#define DD 128
#define HH 256
#define MM (BB*TT)     // 16384
#define NN (DD*DD)     // 16384
#define KK HH          // 256
#define KSPLIT 768     // 3*KK : A=[hi|hi|lo], B=[hi|lo|hi]

// Device scratch (allocation-free rule)
__device__ __align__(128) __nv_bfloat16 g_A2[(size_t)MM * KSPLIT];   // 25 MB
__device__ __align__(128) __nv_bfloat16 g_B2T[(size_t)NN * KSPLIT];  // 25 MB
__device__ __align__(128) float g_trans[(size_t)MM * NN];            // 1.07 GB

// ---------------------------------------------------------------------------
// PTX helpers (sm_80-class only — harness ptxas targets base sm_103)
// ---------------------------------------------------------------------------
__device__ __forceinline__ uint32_t smem_u32(const void* p) {
    uint32_t a;
    asm("{ .reg .u64 t; cvta.to.shared.u64 t, %1; cvt.u32.u64 %0, t; }" : "=r"(a) : "l"(p));
    return a;
}
__device__ __forceinline__ void cp16(uint32_t dst, const void* src) {
    asm volatile("cp.async.cg.shared.global [%0], [%1], 16;" :: "r"(dst), "l"(src) : "memory");
}
__device__ __forceinline__ void cp_commit() {
    asm volatile("cp.async.commit_group;" ::: "memory");
}
template <int N>
__device__ __forceinline__ void cp_wait() {
    asm volatile("cp.async.wait_group %0;" :: "n"(N) : "memory");
}
__device__ __forceinline__ void ldsm4(uint32_t* r, uint32_t addr) {
    asm volatile("ldmatrix.sync.aligned.m8n8.x4.shared.b16 {%0,%1,%2,%3}, [%4];"
                 : "=r"(r[0]), "=r"(r[1]), "=r"(r[2]), "=r"(r[3]) : "r"(addr));
}
__device__ __forceinline__ void mma_bf16(float* d, const uint32_t* a, const uint32_t* b) {
    asm volatile(
        "mma.sync.aligned.m16n8k16.row.col.f32.bf16.bf16.f32 "
        "{%0,%1,%2,%3}, {%4,%5,%6,%7}, {%8,%9}, {%0,%1,%2,%3};"
        : "+f"(d[0]), "+f"(d[1]), "+f"(d[2]), "+f"(d[3])
        : "r"(a[0]), "r"(a[1]), "r"(a[2]), "r"(a[3]), "r"(b[0]), "r"(b[1]));
}
// SW128 swizzle, closed form for row*128+kb (kb < 128)
__device__ __forceinline__ uint32_t swoff(uint32_t row, uint32_t kb) {
    return row * 128u + (kb ^ ((row & 7u) << 4));
}

// ---------------------------------------------------------------------------
// Kernel 1: h = relu(actions@w1+b1); write A2 = [hi | hi | lo] bf16 rows
// ---------------------------------------------------------------------------
__global__ __launch_bounds__(256) void mlp1_kernel(const float* __restrict__ actions,
                                                   const float* __restrict__ w1,
                                                   const float* __restrict__ b1)
{
    __shared__ float as[8][AA];
    const int tid = threadIdx.x;
    const int m0 = blockIdx.x * 8;

    for (int i = tid; i < 8 * AA; i += 256)
        as[i >> 6][i & 63] = actions[(size_t)m0 * AA + i];
    __syncthreads();

    const int n = tid;
    float bv = b1[n];
    float acc[8];
#pragma unroll
    for (int r = 0; r < 8; r++) acc[r] = bv;
#pragma unroll 8
    for (int a = 0; a < AA; a++) {
        float w = w1[(size_t)a * HH + n];
#pragma unroll
        for (int r = 0; r < 8; r++) acc[r] = fmaf(as[r][a], w, acc[r]);
    }
#pragma unroll
    for (int r = 0; r < 8; r++) {
        float v = fmaxf(acc[r], 0.0f);
        __nv_bfloat16 hi = __float2bfloat16_rn(v);
        __nv_bfloat16 lo = __float2bfloat16_rn(v - __bfloat162float(hi));
        size_t row = (size_t)(m0 + r) * KSPLIT;
        g_A2[row + n] = hi;
        g_A2[row + KK + n] = hi;
        g_A2[row + 2 * KK + n] = lo;
    }
}

// ---------------------------------------------------------------------------
// Kernel 1b: B2T[n, :] = [hi(w2[:,n]) | lo(w2[:,n]) | hi(w2[:,n])]  (transpose)
// ---------------------------------------------------------------------------
__global__ __launch_bounds__(256) void bprep_kernel(const float* __restrict__ w2)
{
    __shared__ float tile[32][33];
    const int tx = threadIdx.x;          // 0..31
    const int ty = threadIdx.y;          // 0..7
    const int n0 = blockIdx.x * 32;
    const int k0 = blockIdx.y * 32;
#pragma unroll
    for (int i = 0; i < 4; i++) {
        int k = k0 + ty + i * 8;
        tile[ty + i * 8][tx] = w2[(size_t)k * NN + n0 + tx];
    }
    __syncthreads();
#pragma unroll
    for (int i = 0; i < 4; i++) {
        int nrow = ty + i * 8;
        float v = tile[tx][nrow];        // w2[k0+tx, n0+nrow]
        __nv_bfloat16 hi = __float2bfloat16_rn(v);
        __nv_bfloat16 lo = __float2bfloat16_rn(v - __bfloat162float(hi));
        size_t row = (size_t)(n0 + nrow) * KSPLIT + k0 + tx;
        g_B2T[row] = hi;
        g_B2T[row + KK] = lo;
        g_B2T[row + 2 * KK] = hi;
    }
}

// ---------------------------------------------------------------------------
// Kernel 2: bf16 mma.sync GEMM  trans = A2 @ B2T^T + b2
// BM=256, BN=128, BK=64 (128B rows, SW128), 4-stage cp.async, ONE barrier
// per k-tile. 512 threads = 16 warps (4x4 grid, 64x32 warp tiles).
// ---------------------------------------------------------------------------
#define BMG 256
#define BNG 128
#define BKG 64
#define NKT (KSPLIT/BKG)     // 12
#define NSTG 4
#define A_BYTES (BMG*128)    // 32768
#define B_BYTES (BNG*128)    // 16384
#define STAGE_BYTES (A_BYTES + B_BYTES)  // 49152

__global__ __launch_bounds__(512, 1) void gemm5_kernel(const float* __restrict__ bias)
{
    extern __shared__ char dsm[];
    __shared__ float bias_s[BNG];

    const uint32_t dyn = smem_u32(dsm);
    const int tid = threadIdx.x;
    const int wid = tid >> 5;
    const int lane = tid & 31;
    const int m0 = blockIdx.y * BMG;
    const int n0 = blockIdx.x * BNG;

    if (tid < BNG) bias_s[tid] = bias[n0 + tid];

    const char* Abase = (const char*)g_A2;
    const char* Bbase = (const char*)g_B2T;

    auto load_stage = [&](int s, int kt) {
        uint32_t sb = dyn + s * STAGE_BYTES;
        size_t kbyte = (size_t)kt * (BKG * 2);   // 128 B per k-tile
#pragma unroll
        for (int i = 0; i < 4; i++) {            // A: 2048 chunks of 16B
            int q = i * 512 + tid;
            uint32_t r = q >> 3, c = (q & 7) * 16;
            cp16(sb + swoff(r, c),
                 Abase + (size_t)(m0 + r) * (KSPLIT * 2) + kbyte + c);
        }
#pragma unroll
        for (int i = 0; i < 2; i++) {            // B: 1024 chunks
            int q = i * 512 + tid;
            uint32_t r = q >> 3, c = (q & 7) * 16;
            cp16(sb + A_BYTES + swoff(r, c),
                 Bbase + (size_t)(n0 + r) * (KSPLIT * 2) + kbyte + c);
        }
        cp_commit();
    };

    // prologue: 2 stages in flight
    load_stage(0, 0);
    load_stage(1, 1);

    // warp tiling: 4 (m) x 4 (n) warps, each 64x32
    const int m_w = (wid >> 2) * 64;
    const int n_w = (wid & 3) * 32;

    const uint32_t a_row = m_w + (lane & 7) + (lane & 8);          // + mi*16
    const uint32_t a_kb  = (lane >> 4) << 4;                       // + ks*32
    const uint32_t b_row = n_w + (lane & 7) + ((lane >> 4) << 3);  // + nj*16
    const uint32_t b_kb  = (lane & 8) << 1;                        // + ks*32

    float acc[4][4][4];
#pragma unroll
    for (int mi = 0; mi < 4; mi++)
#pragma unroll
        for (int nt = 0; nt < 4; nt++)
#pragma unroll
            for (int e = 0; e < 4; e++) acc[mi][nt][e] = 0.0f;

#pragma unroll 1
    for (int kt = 0; kt < NKT; kt++) {
        const int s = kt % NSTG;
        if (kt + 2 < NKT) load_stage((kt + 2) % NSTG, kt + 2);

        if (kt + 2 < NKT)      cp_wait<2>();
        else if (kt + 1 < NKT) cp_wait<1>();
        else                   cp_wait<0>();
        __syncthreads();   // single barrier per tile (safe with NSTG=4)

        const uint32_t abase = dyn + s * STAGE_BYTES;
        const uint32_t bbase = abase + A_BYTES;

#pragma unroll
        for (int ks = 0; ks < 4; ks++) {
            uint32_t af[4][4], bf[2][4];
#pragma unroll
            for (int mi = 0; mi < 4; mi++)
                ldsm4(af[mi], abase + swoff(a_row + mi * 16, a_kb + ks * 32));
#pragma unroll
            for (int nj = 0; nj < 2; nj++)
                ldsm4(bf[nj], bbase + swoff(b_row + nj * 16, b_kb + ks * 32));
#pragma unroll
            for (int mi = 0; mi < 4; mi++)
#pragma unroll
                for (int nj = 0; nj < 2; nj++) {
                    mma_bf16(acc[mi][2 * nj],     af[mi], &bf[nj][0]);
                    mma_bf16(acc[mi][2 * nj + 1], af[mi], &bf[nj][2]);
                }
        }
    }

    // epilogue: direct float2 stores with bias
    const int cl = 2 * (lane & 3);
    const int rl = lane >> 2;
#pragma unroll
    for (int mi = 0; mi < 4; mi++) {
        int row0 = m0 + m_w + mi * 16 + rl;
#pragma unroll
        for (int nt = 0; nt < 4; nt++) {
            int lc = n_w + nt * 8 + cl;
            int col = n0 + lc;
            float bx = bias_s[lc], by = bias_s[lc + 1];
            float2 v0 = {acc[mi][nt][0] + bx, acc[mi][nt][1] + by};
            float2 v1 = {acc[mi][nt][2] + bx, acc[mi][nt][3] + by};
            *(float2*)(g_trans + (size_t)row0 * NN + col) = v0;
            *(float2*)(g_trans + (size_t)(row0 + 8) * NN + col) = v1;
        }
    }
}

// ---------------------------------------------------------------------------
// Kernel 3: sequential scan, cp.async triple-buffered T staging (distance 2),
// 3 barriers/step, no serialized norm. One CTA per batch, 512 threads.
// ---------------------------------------------------------------------------
#define SC_BUF 65536                     // one T matrix (128*128*4)
#define SC_SMEM (3 * SC_BUF)

__global__ __launch_bounds__(512, 1) void scan_kernel(const float* __restrict__ init_s,
                                                      float* __restrict__ out)
{
    extern __shared__ char ssm[];        // 3 T buffers
    __shared__ float s_sm[DD];
    __shared__ float red[16][DD];
    __shared__ float wsum[4];
    __shared__ float inv0;

    const int tid = threadIdx.x;
    const int b = blockIdx.x;
    const uint32_t sbase = smem_u32(ssm);
    const char* Tb = (const char*)(g_trans + (size_t)b * TT * (DD * DD));

    auto loadT = [&](int t) {
        uint32_t db = sbase + (uint32_t)(t % 3) * SC_BUF;
        const char* src = Tb + (size_t)t * SC_BUF;
#pragma unroll
        for (int i = 0; i < 8; i++) {
            int q = i * 512 + tid;
            cp16(db + q * 16, src + (size_t)q * 16);
        }
        cp_commit();
    };

    // prefetch T(0), T(1)
    loadT(0);
    loadT(1);

    // s0 = l2norm(init_structure)
    if (tid < DD) {
        float v = init_s[tid];
        s_sm[tid] = v;
        red[0][tid] = v * v;
    }
    __syncthreads();
    if (tid == 0) {
        float s = 0.0f;
        for (int i = 0; i < DD; i++) s += red[0][i];
        inv0 = 1.0f / fmaxf(sqrtf(s), 1e-12f);
    }
    __syncthreads();
    if (tid < DD) s_sm[tid] *= inv0;
    // NOTE: next barrier (BAR1 of step 0) orders this write before reads.

    const int c = tid >> 5;              // 0..15 : 8-row chunk
    const int j = (tid & 31) * 4;        // 4-col group

    for (int t = 0; t < TT; t++) {
        if (t == TT - 1) cp_wait<0>();
        else             cp_wait<1>();
        __syncthreads();                 // BAR1: buf t landed everywhere; step t-1 done

        if (t + 2 < TT) loadT(t + 2);    // overwrites buf (t-1)%3 — readers done pre-BAR1

        const float* Tm = (const float*)(ssm + (t % 3) * SC_BUF);
        float4 p = {0.0f, 0.0f, 0.0f, 0.0f};
#pragma unroll
        for (int ii = 0; ii < 8; ii++) {
            int i = c * 8 + ii;
            float sv = s_sm[i];
            float4 tv = *(const float4*)(Tm + (size_t)i * DD + j);
            p.x = fmaf(sv, tv.x, p.x);
            p.y = fmaf(sv, tv.y, p.y);
            p.z = fmaf(sv, tv.z, p.z);
            p.w = fmaf(sv, tv.w, p.w);
        }
        *(float4*)&red[c][j] = p;
        __syncthreads();                 // BAR2

        float v = 0.0f, sq = 0.0f;
        if (tid < DD) {
            // balanced tree over 16 partials
            float s0 = red[0][tid] + red[1][tid];
            float s1 = red[2][tid] + red[3][tid];
            float s2 = red[4][tid] + red[5][tid];
            float s3 = red[6][tid] + red[7][tid];
            float s4 = red[8][tid] + red[9][tid];
            float s5 = red[10][tid] + red[11][tid];
            float s6 = red[12][tid] + red[13][tid];
            float s7 = red[14][tid] + red[15][tid];
            v = ((s0 + s1) + (s2 + s3)) + ((s4 + s5) + (s6 + s7));
            v = fmaxf(v, 0.0f);
            sq = v * v;
        }
#pragma unroll
        for (int o = 16; o; o >>= 1) sq += __shfl_xor_sync(0xffffffffu, sq, o);
        if (tid < DD && (tid & 31) == 0) wsum[tid >> 5] = sq;
        __syncthreads();                 // BAR3

        float inv = rsqrtf(fmaxf((wsum[0] + wsum[1]) + (wsum[2] + wsum[3]), 1e-24f));
        if (tid < DD) {
            float sn = v * inv;
            s_sm[tid] = sn;
            out[((size_t)b * TT + t) * DD + tid] = sn;
        }
        // next-iteration BAR1 orders s_sm write before reads
    }
}

// ---------------------------------------------------------------------------
extern "C" void kernel_launch(void* const* d_in, const int* in_sizes, int n_in,
                              void* d_out, int out_size)
{
    const float* actions = (const float*)d_in[0];
    const float* init_s  = (const float*)d_in[1];
    const float* w1      = (const float*)d_in[2];
    const float* b1      = (const float*)d_in[3];
    const float* w2      = (const float*)d_in[4];
    const float* b2      = (const float*)d_in[5];
    float* out = (float*)d_out;

    cudaFuncSetAttribute(gemm5_kernel, cudaFuncAttributeMaxDynamicSharedMemorySize,
                         NSTG * STAGE_BYTES);
    cudaFuncSetAttribute(scan_kernel, cudaFuncAttributeMaxDynamicSharedMemorySize,
                         SC_SMEM);

    mlp1_kernel<<<MM / 8, 256>>>(actions, w1, b1);
    bprep_kernel<<<dim3(NN / 32, KK / 32), dim3(32, 8)>>>(w2);
    gemm5_kernel<<<dim3(NN / BNG, MM / BMG), 512, NSTG * STAGE_BYTES>>>(b2);
    scan_kernel<<<BB, 512, SC_SMEM>>>(init_s, out);
}

// round 6
// speedup vs baseline: 1.2592x; 1.2592x over previous
#include <cuda_runtime.h>
#include <cuda_bf16.h>
#include <math.h>
#include <stdint.h>

// Shapes (fixed)
#define BB 32
#define TT 512
#define AA 64
#define DD 128
#define HH 256
#define MM (BB*TT)     // 16384
#define NN (DD*DD)     // 16384
#define KK HH          // 256
#define KSPLIT 768     // 3*KK : A=[hi|hi|lo], B=[hi|lo|hi]

// Device scratch (allocation-free rule)
__device__ __align__(128) __nv_bfloat16 g_A2[(size_t)MM * KSPLIT];   // 25 MB
__device__ __align__(128) __nv_bfloat16 g_B2T[(size_t)NN * KSPLIT];  // 25 MB
__device__ __align__(128) float g_trans[(size_t)MM * NN];            // 1.07 GB

// ---------------------------------------------------------------------------
// PTX helpers (sm_80-class only — harness ptxas targets base sm_103)
// ---------------------------------------------------------------------------
__device__ __forceinline__ uint32_t smem_u32(const void* p) {
    uint32_t a;
    asm("{ .reg .u64 t; cvta.to.shared.u64 t, %1; cvt.u32.u64 %0, t; }" : "=r"(a) : "l"(p));
    return a;
}
__device__ __forceinline__ void cp16(uint32_t dst, const void* src) {
    asm volatile("cp.async.cg.shared.global [%0], [%1], 16;" :: "r"(dst), "l"(src) : "memory");
}
__device__ __forceinline__ void cp_commit() {
    asm volatile("cp.async.commit_group;" ::: "memory");
}
template <int N>
__device__ __forceinline__ void cp_wait() {
    asm volatile("cp.async.wait_group %0;" :: "n"(N) : "memory");
}
__device__ __forceinline__ void ldsm4(uint32_t* r, uint32_t addr) {
    asm volatile("ldmatrix.sync.aligned.m8n8.x4.shared.b16 {%0,%1,%2,%3}, [%4];"
                 : "=r"(r[0]), "=r"(r[1]), "=r"(r[2]), "=r"(r[3]) : "r"(addr));
}
__device__ __forceinline__ void mma_bf16(float* d, const uint32_t* a, const uint32_t* b) {
    asm volatile(
        "mma.sync.aligned.m16n8k16.row.col.f32.bf16.bf16.f32 "
        "{%0,%1,%2,%3}, {%4,%5,%6,%7}, {%8,%9}, {%0,%1,%2,%3};"
        : "+f"(d[0]), "+f"(d[1]), "+f"(d[2]), "+f"(d[3])
        : "r"(a[0]), "r"(a[1]), "r"(a[2]), "r"(a[3]), "r"(b[0]), "r"(b[1]));
}
__device__ __forceinline__ void l2pref(const void* p) {
    asm volatile("prefetch.global.L2 [%0];" :: "l"(p));
}
// SW128 swizzle, closed form for row*128+kb (kb < 128)
__device__ __forceinline__ uint32_t swoff(uint32_t row, uint32_t kb) {
    return row * 128u + (kb ^ ((row & 7u) << 4));
}

// ---------------------------------------------------------------------------
// Kernel 1: h = relu(actions@w1+b1); write A2 = [hi | hi | lo] bf16 rows
// ---------------------------------------------------------------------------
__global__ __launch_bounds__(256) void mlp1_kernel(const float* __restrict__ actions,
                                                   const float* __restrict__ w1,
                                                   const float* __restrict__ b1)
{
    __shared__ float as[8][AA];
    const int tid = threadIdx.x;
    const int m0 = blockIdx.x * 8;

    for (int i = tid; i < 8 * AA; i += 256)
        as[i >> 6][i & 63] = actions[(size_t)m0 * AA + i];
    __syncthreads();

    const int n = tid;
    float bv = b1[n];
    float acc[8];
#pragma unroll
    for (int r = 0; r < 8; r++) acc[r] = bv;
#pragma unroll 8
    for (int a = 0; a < AA; a++) {
        float w = w1[(size_t)a * HH + n];
#pragma unroll
        for (int r = 0; r < 8; r++) acc[r] = fmaf(as[r][a], w, acc[r]);
    }
#pragma unroll
    for (int r = 0; r < 8; r++) {
        float v = fmaxf(acc[r], 0.0f);
        __nv_bfloat16 hi = __float2bfloat16_rn(v);
        __nv_bfloat16 lo = __float2bfloat16_rn(v - __bfloat162float(hi));
        size_t row = (size_t)(m0 + r) * KSPLIT;
        g_A2[row + n] = hi;
        g_A2[row + KK + n] = hi;
        g_A2[row + 2 * KK + n] = lo;
    }
}

// ---------------------------------------------------------------------------
// Kernel 1b: B2T[n, :] = [hi(w2[:,n]) | lo(w2[:,n]) | hi(w2[:,n])]  (transpose)
// ---------------------------------------------------------------------------
__global__ __launch_bounds__(256) void bprep_kernel(const float* __restrict__ w2)
{
    __shared__ float tile[32][33];
    const int tx = threadIdx.x;          // 0..31
    const int ty = threadIdx.y;          // 0..7
    const int n0 = blockIdx.x * 32;
    const int k0 = blockIdx.y * 32;
#pragma unroll
    for (int i = 0; i < 4; i++) {
        int k = k0 + ty + i * 8;
        tile[ty + i * 8][tx] = w2[(size_t)k * NN + n0 + tx];
    }
    __syncthreads();
#pragma unroll
    for (int i = 0; i < 4; i++) {
        int nrow = ty + i * 8;
        float v = tile[tx][nrow];        // w2[k0+tx, n0+nrow]
        __nv_bfloat16 hi = __float2bfloat16_rn(v);
        __nv_bfloat16 lo = __float2bfloat16_rn(v - __bfloat162float(hi));
        size_t row = (size_t)(n0 + nrow) * KSPLIT + k0 + tx;
        g_B2T[row] = hi;
        g_B2T[row + KK] = lo;
        g_B2T[row + 2 * KK] = hi;
    }
}

// ---------------------------------------------------------------------------
// Kernel 2: bf16 mma.sync GEMM (EXACT Round-4 configuration — measured good)
// BM=256, BN=128, BK=64 (SW128), 3-stage cp.async, 512 threads = 16 warps.
// ---------------------------------------------------------------------------
#define BMG 256
#define BNG 128
#define BKG 64
#define NKT (KSPLIT/BKG)     // 12
#define NSTG 3
#define A_BYTES (BMG*128)    // 32768
#define B_BYTES (BNG*128)    // 16384
#define STAGE_BYTES (A_BYTES + B_BYTES)  // 49152

__global__ __launch_bounds__(512, 1) void gemm4_kernel(const float* __restrict__ bias)
{
    extern __shared__ char dsm[];
    __shared__ float bias_s[BNG];

    const uint32_t dyn = smem_u32(dsm);
    const int tid = threadIdx.x;
    const int wid = tid >> 5;
    const int lane = tid & 31;
    const int m0 = blockIdx.y * BMG;
    const int n0 = blockIdx.x * BNG;

    if (tid < BNG) bias_s[tid] = bias[n0 + tid];

    const char* Abase = (const char*)g_A2;
    const char* Bbase = (const char*)g_B2T;

    auto load_stage = [&](int s, int kt) {
        uint32_t sb = dyn + s * STAGE_BYTES;
        size_t kbyte = (size_t)kt * (BKG * 2);
#pragma unroll
        for (int i = 0; i < 4; i++) {
            int q = i * 512 + tid;
            uint32_t r = q >> 3, c = (q & 7) * 16;
            cp16(sb + swoff(r, c),
                 Abase + (size_t)(m0 + r) * (KSPLIT * 2) + kbyte + c);
        }
#pragma unroll
        for (int i = 0; i < 2; i++) {
            int q = i * 512 + tid;
            uint32_t r = q >> 3, c = (q & 7) * 16;
            cp16(sb + A_BYTES + swoff(r, c),
                 Bbase + (size_t)(n0 + r) * (KSPLIT * 2) + kbyte + c);
        }
        cp_commit();
    };

    load_stage(0, 0);
    load_stage(1, 1);

    const int m_w = (wid >> 2) * 64;
    const int n_w = (wid & 3) * 32;

    const uint32_t a_row = m_w + (lane & 7) + (lane & 8);
    const uint32_t a_kb  = (lane >> 4) << 4;
    const uint32_t b_row = n_w + (lane & 7) + ((lane >> 4) << 3);
    const uint32_t b_kb  = (lane & 8) << 1;

    float acc[4][4][4];
#pragma unroll
    for (int mi = 0; mi < 4; mi++)
#pragma unroll
        for (int nt = 0; nt < 4; nt++)
#pragma unroll
            for (int e = 0; e < 4; e++) acc[mi][nt][e] = 0.0f;

#pragma unroll 1
    for (int kt = 0; kt < NKT; kt++) {
        const int s = kt % NSTG;
        if (kt + 2 < NKT) load_stage((kt + 2) % NSTG, kt + 2);

        if (kt + 2 < NKT)      cp_wait<2>();
        else if (kt + 1 < NKT) cp_wait<1>();
        else                   cp_wait<0>();
        __syncthreads();

        const uint32_t abase = dyn + s * STAGE_BYTES;
        const uint32_t bbase = abase + A_BYTES;

#pragma unroll
        for (int ks = 0; ks < 4; ks++) {
            uint32_t af[4][4], bf[2][4];
#pragma unroll
            for (int mi = 0; mi < 4; mi++)
                ldsm4(af[mi], abase + swoff(a_row + mi * 16, a_kb + ks * 32));
#pragma unroll
            for (int nj = 0; nj < 2; nj++)
                ldsm4(bf[nj], bbase + swoff(b_row + nj * 16, b_kb + ks * 32));
#pragma unroll
            for (int mi = 0; mi < 4; mi++)
#pragma unroll
                for (int nj = 0; nj < 2; nj++) {
                    mma_bf16(acc[mi][2 * nj],     af[mi], &bf[nj][0]);
                    mma_bf16(acc[mi][2 * nj + 1], af[mi], &bf[nj][2]);
                }
        }
        __syncthreads();
    }

    const int cl = 2 * (lane & 3);
    const int rl = lane >> 2;
#pragma unroll
    for (int mi = 0; mi < 4; mi++) {
        int row0 = m0 + m_w + mi * 16 + rl;
#pragma unroll
        for (int nt = 0; nt < 4; nt++) {
            int lc = n_w + nt * 8 + cl;
            int col = n0 + lc;
            float bx = bias_s[lc], by = bias_s[lc + 1];
            float2 v0 = {acc[mi][nt][0] + bx, acc[mi][nt][1] + by};
            float2 v1 = {acc[mi][nt][2] + bx, acc[mi][nt][3] + by};
            *(float2*)(g_trans + (size_t)row0 * NN + col) = v0;
            *(float2*)(g_trans + (size_t)(row0 + 8) * NN + col) = v1;
        }
    }
}

// ---------------------------------------------------------------------------
// Kernel 3: scan with pipelined (one-step-deferred) normalization.
// Scale invariance of relu+matvec means the recurrence never needs the norm;
// out[t-1] is normalized and stored during step t. 2 barriers per step.
// Register prefetch of T(t+1) + L2 prefetch of T(t+2).
// ---------------------------------------------------------------------------
__global__ __launch_bounds__(512, 1) void scan_kernel(const float* __restrict__ init_s,
                                                      float* __restrict__ out)
{
    __shared__ float s_sm[DD];
    __shared__ float red[16][DD];
    __shared__ float wsum[4];

    const int tid = threadIdx.x;
    const int b = blockIdx.x;
    const int c = tid >> 5;              // 0..15 : 8-row chunk
    const int j = (tid & 31) * 4;        // 4-col group
    const float* Tb = g_trans + (size_t)b * TT * (DD * DD);

    // s0 unnormalized — recurrence is scale-invariant, s0 not emitted.
    if (tid < DD) s_sm[tid] = init_s[tid];

    // prefetch T(0) into registers; hint T(1) into L2
    float4 cur[8];
#pragma unroll
    for (int ii = 0; ii < 8; ii++)
        cur[ii] = *(const float4*)(Tb + (size_t)(c * 8 + ii) * DD + j);
    l2pref(Tb + (size_t)1 * (DD * DD) + (size_t)(c * 8) * DD + j);
    __syncthreads();                     // BAR_A (t=0)

    float vprev = 0.0f;

    for (int t = 0; t < TT; t++) {
        // register prefetch T(t+1); L2 prefetch T(t+2)
        float4 nxt[8];
        if (t + 1 < TT) {
            const float* Tn = Tb + (size_t)(t + 1) * (DD * DD);
#pragma unroll
            for (int ii = 0; ii < 8; ii++)
                nxt[ii] = *(const float4*)(Tn + (size_t)(c * 8 + ii) * DD + j);
        }
        if (t + 2 < TT) {
            const float* Tp = Tb + (size_t)(t + 2) * (DD * DD);
#pragma unroll
            for (int ii = 0; ii < 8; ii++)
                l2pref(Tp + (size_t)(c * 8 + ii) * DD + j);
        }

        // matvec partial: p_j += s_i * T[i][j] over this thread's 8 rows
        float4 p = {0.0f, 0.0f, 0.0f, 0.0f};
#pragma unroll
        for (int ii = 0; ii < 8; ii++) {
            float sv = s_sm[c * 8 + ii];
            p.x = fmaf(sv, cur[ii].x, p.x);
            p.y = fmaf(sv, cur[ii].y, p.y);
            p.z = fmaf(sv, cur[ii].z, p.z);
            p.w = fmaf(sv, cur[ii].w, p.w);
        }
        *(float4*)&red[c][j] = p;

        // pipelined: reduce ||vprev||^2 (step t-1) while matvec drains
        float sq = vprev * vprev;
#pragma unroll
        for (int o = 16; o; o >>= 1) sq += __shfl_xor_sync(0xffffffffu, sq, o);
        if (tid < DD && (tid & 31) == 0) wsum[c] = sq;   // warps 0..3 only
        __syncthreads();                 // BAR_B

        if (tid < DD) {
            // balanced tree over 16 partial rows
            float s0 = red[0][tid] + red[1][tid];
            float s1 = red[2][tid] + red[3][tid];
            float s2 = red[4][tid] + red[5][tid];
            float s3 = red[6][tid] + red[7][tid];
            float s4 = red[8][tid] + red[9][tid];
            float s5 = red[10][tid] + red[11][tid];
            float s6 = red[12][tid] + red[13][tid];
            float s7 = red[14][tid] + red[15][tid];
            float v = ((s0 + s1) + (s2 + s3)) + ((s4 + s5) + (s6 + s7));
            v = fmaxf(v, 0.0f);

            // finish step t-1: exact normalization of vprev
            float inv = rsqrtf(fmaxf((wsum[0] + wsum[1]) + (wsum[2] + wsum[3]), 1e-24f));
            if (t > 0)
                out[((size_t)b * TT + (t - 1)) * DD + tid] = vprev * inv;

            // carry v forward; scale by stale inv purely for range control
            s_sm[tid] = (t > 0) ? v * inv : v;
            vprev = v;
        }
#pragma unroll
        for (int ii = 0; ii < 8; ii++) cur[ii] = nxt[ii];
        __syncthreads();                 // BAR_A (next step)
    }

    // drain: emit out[TT-1]
    float sq = vprev * vprev;
#pragma unroll
    for (int o = 16; o; o >>= 1) sq += __shfl_xor_sync(0xffffffffu, sq, o);
    if (tid < DD && (tid & 31) == 0) wsum[c] = sq;
    __syncthreads();
    if (tid < DD) {
        float inv = rsqrtf(fmaxf((wsum[0] + wsum[1]) + (wsum[2] + wsum[3]), 1e-24f));
        out[((size_t)b * TT + (TT - 1)) * DD + tid] = vprev * inv;
    }
}

// ---------------------------------------------------------------------------
extern "C" void kernel_launch(void* const* d_in, const int* in_sizes, int n_in,
                              void* d_out, int out_size)
{
    const float* actions = (const float*)d_in[0];
    const float* init_s  = (const float*)d_in[1];
    const float* w1      = (const float*)d_in[2];
    const float* b1      = (const float*)d_in[3];
    const float* w2      = (const float*)d_in[4];
    const float* b2      = (const float*)d_in[5];
    float* out = (float*)d_out;

    cudaFuncSetAttribute(gemm4_kernel, cudaFuncAttributeMaxDynamicSharedMemorySize,
                         NSTG * STAGE_BYTES);

    mlp1_kernel<<<MM / 8, 256>>>(actions, w1, b1);
    bprep_kernel<<<dim3(NN / 32, KK / 32), dim3(32, 8)>>>(w2);
    gemm4_kernel<<<dim3(NN / BNG, MM / BMG), 512, NSTG * STAGE_BYTES>>>(b2);
    scan_kernel<<<BB, 512>>>(init_s, out);
}

// round 7
// speedup vs baseline: 1.5135x; 1.2020x over previous
#include <cuda_runtime.h>
#include <cuda_bf16.h>
#include <math.h>
#include <stdint.h>

// Shapes (fixed)
#define BB 32
#define TT 512
#define AA 64
#define DD 128
#define HH 256
#define MM (BB*TT)     // 16384
#define NN (DD*DD)     // 16384
#define KK HH          // 256
#define KSPLIT 768     // 3*KK : A=[hi|hi|lo], B=[hi|lo|hi]

// Device scratch (allocation-free rule)
__device__ __align__(128) __nv_bfloat16 g_A2[(size_t)MM * KSPLIT];   // 25 MB
__device__ __align__(128) __nv_bfloat16 g_B2T[(size_t)NN * KSPLIT];  // 25 MB
__device__ __align__(128) float g_trans[(size_t)MM * NN];            // 1.07 GB

// ---------------------------------------------------------------------------
// PTX helpers (sm_80-class only — harness ptxas targets base sm_103)
// ---------------------------------------------------------------------------
__device__ __forceinline__ uint32_t smem_u32(const void* p) {
    uint32_t a;
    asm("{ .reg .u64 t; cvta.to.shared.u64 t, %1; cvt.u32.u64 %0, t; }" : "=r"(a) : "l"(p));
    return a;
}
__device__ __forceinline__ void cp16(uint32_t dst, const void* src) {
    asm volatile("cp.async.cg.shared.global [%0], [%1], 16;" :: "r"(dst), "l"(src) : "memory");
}
__device__ __forceinline__ void cp_commit() {
    asm volatile("cp.async.commit_group;" ::: "memory");
}
template <int N>
__device__ __forceinline__ void cp_wait() {
    asm volatile("cp.async.wait_group %0;" :: "n"(N) : "memory");
}
__device__ __forceinline__ void ldsm4(uint32_t* r, uint32_t addr) {
    asm volatile("ldmatrix.sync.aligned.m8n8.x4.shared.b16 {%0,%1,%2,%3}, [%4];"
                 : "=r"(r[0]), "=r"(r[1]), "=r"(r[2]), "=r"(r[3]) : "r"(addr));
}
__device__ __forceinline__ void mma_bf16(float* d, const uint32_t* a, const uint32_t* b) {
    asm volatile(
        "mma.sync.aligned.m16n8k16.row.col.f32.bf16.bf16.f32 "
        "{%0,%1,%2,%3}, {%4,%5,%6,%7}, {%8,%9}, {%0,%1,%2,%3};"
        : "+f"(d[0]), "+f"(d[1]), "+f"(d[2]), "+f"(d[3])
        : "r"(a[0]), "r"(a[1]), "r"(a[2]), "r"(a[3]), "r"(b[0]), "r"(b[1]));
}
// SW128 swizzle, closed form for row*128+kb (kb < 128)
__device__ __forceinline__ uint32_t swoff(uint32_t row, uint32_t kb) {
    return row * 128u + (kb ^ ((row & 7u) << 4));
}

// ---------------------------------------------------------------------------
// Kernel 1: h = relu(actions@w1+b1); write A2 = [hi | hi | lo] bf16 rows
// ---------------------------------------------------------------------------
__global__ __launch_bounds__(256) void mlp1_kernel(const float* __restrict__ actions,
                                                   const float* __restrict__ w1,
                                                   const float* __restrict__ b1)
{
    __shared__ float as[8][AA];
    const int tid = threadIdx.x;
    const int m0 = blockIdx.x * 8;

    for (int i = tid; i < 8 * AA; i += 256)
        as[i >> 6][i & 63] = actions[(size_t)m0 * AA + i];
    __syncthreads();

    const int n = tid;
    float bv = b1[n];
    float acc[8];
#pragma unroll
    for (int r = 0; r < 8; r++) acc[r] = bv;
#pragma unroll 8
    for (int a = 0; a < AA; a++) {
        float w = w1[(size_t)a * HH + n];
#pragma unroll
        for (int r = 0; r < 8; r++) acc[r] = fmaf(as[r][a], w, acc[r]);
    }
#pragma unroll
    for (int r = 0; r < 8; r++) {
        float v = fmaxf(acc[r], 0.0f);
        __nv_bfloat16 hi = __float2bfloat16_rn(v);
        __nv_bfloat16 lo = __float2bfloat16_rn(v - __bfloat162float(hi));
        size_t row = (size_t)(m0 + r) * KSPLIT;
        g_A2[row + n] = hi;
        g_A2[row + KK + n] = hi;
        g_A2[row + 2 * KK + n] = lo;
    }
}

// ---------------------------------------------------------------------------
// Kernel 1b: B2T[n, :] = [hi(w2[:,n]) | lo(w2[:,n]) | hi(w2[:,n])]  (transpose)
// ---------------------------------------------------------------------------
__global__ __launch_bounds__(256) void bprep_kernel(const float* __restrict__ w2)
{
    __shared__ float tile[32][33];
    const int tx = threadIdx.x;          // 0..31
    const int ty = threadIdx.y;          // 0..7
    const int n0 = blockIdx.x * 32;
    const int k0 = blockIdx.y * 32;
#pragma unroll
    for (int i = 0; i < 4; i++) {
        int k = k0 + ty + i * 8;
        tile[ty + i * 8][tx] = w2[(size_t)k * NN + n0 + tx];
    }
    __syncthreads();
#pragma unroll
    for (int i = 0; i < 4; i++) {
        int nrow = ty + i * 8;
        float v = tile[tx][nrow];        // w2[k0+tx, n0+nrow]
        __nv_bfloat16 hi = __float2bfloat16_rn(v);
        __nv_bfloat16 lo = __float2bfloat16_rn(v - __bfloat162float(hi));
        size_t row = (size_t)(n0 + nrow) * KSPLIT + k0 + tx;
        g_B2T[row] = hi;
        g_B2T[row + KK] = lo;
        g_B2T[row + 2 * KK] = hi;
    }
}

// ---------------------------------------------------------------------------
// Kernel 2: bf16 mma.sync GEMM  trans = A2 @ B2T^T + b2
// BM=128, BN=128, BK=64 (SW128), 3-stage cp.async, 256 threads = 8 warps
// (2x4 grid of 64x32 warp tiles), 2 CTAs/SM for bubble overlap.
// ---------------------------------------------------------------------------
#define BMG 128
#define BNG 128
#define BKG 64
#define NKT (KSPLIT/BKG)     // 12
#define NSTG 3
#define A_BYTES (BMG*128)    // 16384
#define B_BYTES (BNG*128)    // 16384
#define STAGE_BYTES (A_BYTES + B_BYTES)  // 32768

__global__ __launch_bounds__(256, 2) void gemm6_kernel(const float* __restrict__ bias)
{
    extern __shared__ char dsm[];
    __shared__ float bias_s[BNG];

    const uint32_t dyn = smem_u32(dsm);
    const int tid = threadIdx.x;
    const int wid = tid >> 5;
    const int lane = tid & 31;
    const int m0 = blockIdx.y * BMG;
    const int n0 = blockIdx.x * BNG;

    if (tid < BNG) bias_s[tid] = bias[n0 + tid];

    const char* Abase = (const char*)g_A2;
    const char* Bbase = (const char*)g_B2T;

    auto load_stage = [&](int s, int kt) {
        uint32_t sb = dyn + s * STAGE_BYTES;
        size_t kbyte = (size_t)kt * (BKG * 2);   // 128 B per k-tile
#pragma unroll
        for (int i = 0; i < 4; i++) {            // A: 1024 chunks of 16B
            int q = i * 256 + tid;
            uint32_t r = q >> 3, c = (q & 7) * 16;
            cp16(sb + swoff(r, c),
                 Abase + (size_t)(m0 + r) * (KSPLIT * 2) + kbyte + c);
        }
#pragma unroll
        for (int i = 0; i < 4; i++) {            // B: 1024 chunks
            int q = i * 256 + tid;
            uint32_t r = q >> 3, c = (q & 7) * 16;
            cp16(sb + A_BYTES + swoff(r, c),
                 Bbase + (size_t)(n0 + r) * (KSPLIT * 2) + kbyte + c);
        }
        cp_commit();
    };

    // prologue: 2 stages in flight
    load_stage(0, 0);
    load_stage(1, 1);

    // warp tiling: 2 (m) x 4 (n) warps, each 64x32
    const int m_w = (wid >> 2) * 64;
    const int n_w = (wid & 3) * 32;

    const uint32_t a_row = m_w + (lane & 7) + (lane & 8);          // + mi*16
    const uint32_t a_kb  = (lane >> 4) << 4;                       // + ks*32
    const uint32_t b_row = n_w + (lane & 7) + ((lane >> 4) << 3);  // + nj*16
    const uint32_t b_kb  = (lane & 8) << 1;                        // + ks*32

    float acc[4][4][4];
#pragma unroll
    for (int mi = 0; mi < 4; mi++)
#pragma unroll
        for (int nt = 0; nt < 4; nt++)
#pragma unroll
            for (int e = 0; e < 4; e++) acc[mi][nt][e] = 0.0f;

#pragma unroll 1
    for (int kt = 0; kt < NKT; kt++) {
        const int s = kt % NSTG;
        if (kt + 2 < NKT) load_stage((kt + 2) % NSTG, kt + 2);

        if (kt + 2 < NKT)      cp_wait<2>();
        else if (kt + 1 < NKT) cp_wait<1>();
        else                   cp_wait<0>();
        __syncthreads();

        const uint32_t abase = dyn + s * STAGE_BYTES;
        const uint32_t bbase = abase + A_BYTES;

#pragma unroll
        for (int ks = 0; ks < 4; ks++) {
            uint32_t af[4][4], bf[2][4];
#pragma unroll
            for (int mi = 0; mi < 4; mi++)
                ldsm4(af[mi], abase + swoff(a_row + mi * 16, a_kb + ks * 32));
#pragma unroll
            for (int nj = 0; nj < 2; nj++)
                ldsm4(bf[nj], bbase + swoff(b_row + nj * 16, b_kb + ks * 32));
#pragma unroll
            for (int mi = 0; mi < 4; mi++)
#pragma unroll
                for (int nj = 0; nj < 2; nj++) {
                    mma_bf16(acc[mi][2 * nj],     af[mi], &bf[nj][0]);
                    mma_bf16(acc[mi][2 * nj + 1], af[mi], &bf[nj][2]);
                }
        }
        __syncthreads();   // stage s free for reload
    }

    // epilogue: direct float2 stores with bias
    const int cl = 2 * (lane & 3);
    const int rl = lane >> 2;
#pragma unroll
    for (int mi = 0; mi < 4; mi++) {
        int row0 = m0 + m_w + mi * 16 + rl;
#pragma unroll
        for (int nt = 0; nt < 4; nt++) {
            int lc = n_w + nt * 8 + cl;
            int col = n0 + lc;
            float bx = bias_s[lc], by = bias_s[lc + 1];
            float2 v0 = {acc[mi][nt][0] + bx, acc[mi][nt][1] + by};
            float2 v1 = {acc[mi][nt][2] + bx, acc[mi][nt][3] + by};
            *(float2*)(g_trans + (size_t)row0 * NN + col) = v0;
            *(float2*)(g_trans + (size_t)(row0 + 8) * NN + col) = v1;
        }
    }
}

// ---------------------------------------------------------------------------
// Kernel 3: scan with pipelined (one-step-deferred) normalization.
// 2 barriers/step, register prefetch of T(t+1). No L2 prefetch (R6: it
// added LSU issue work and regressed the step time).
// ---------------------------------------------------------------------------
__global__ __launch_bounds__(512, 1) void scan_kernel(const float* __restrict__ init_s,
                                                      float* __restrict__ out)
{
    __shared__ float s_sm[DD];
    __shared__ float red[16][DD];
    __shared__ float wsum[4];

    const int tid = threadIdx.x;
    const int b = blockIdx.x;
    const int c = tid >> 5;              // 0..15 : 8-row chunk
    const int j = (tid & 31) * 4;        // 4-col group
    const float* Tb = g_trans + (size_t)b * TT * (DD * DD);

    // s0 unnormalized — recurrence is scale-invariant, s0 not emitted.
    if (tid < DD) s_sm[tid] = init_s[tid];

    // prefetch T(0) into registers
    float4 cur[8];
#pragma unroll
    for (int ii = 0; ii < 8; ii++)
        cur[ii] = *(const float4*)(Tb + (size_t)(c * 8 + ii) * DD + j);
    __syncthreads();                     // BAR_A (t=0)

    float vprev = 0.0f;

    for (int t = 0; t < TT; t++) {
        // register prefetch T(t+1)
        float4 nxt[8];
        if (t + 1 < TT) {
            const float* Tn = Tb + (size_t)(t + 1) * (DD * DD);
#pragma unroll
            for (int ii = 0; ii < 8; ii++)
                nxt[ii] = *(const float4*)(Tn + (size_t)(c * 8 + ii) * DD + j);
        }

        // matvec partial: p_j += s_i * T[i][j] over this thread's 8 rows
        float4 p = {0.0f, 0.0f, 0.0f, 0.0f};
#pragma unroll
        for (int ii = 0; ii < 8; ii++) {
            float sv = s_sm[c * 8 + ii];
            p.x = fmaf(sv, cur[ii].x, p.x);
            p.y = fmaf(sv, cur[ii].y, p.y);
            p.z = fmaf(sv, cur[ii].z, p.z);
            p.w = fmaf(sv, cur[ii].w, p.w);
        }
        *(float4*)&red[c][j] = p;

        // pipelined: reduce ||vprev||^2 (step t-1) while matvec drains
        float sq = vprev * vprev;
#pragma unroll
        for (int o = 16; o; o >>= 1) sq += __shfl_xor_sync(0xffffffffu, sq, o);
        if (tid < DD && (tid & 31) == 0) wsum[c] = sq;   // warps 0..3 only
        __syncthreads();                 // BAR_B

        if (tid < DD) {
            // balanced tree over 16 partial rows
            float s0 = red[0][tid] + red[1][tid];
            float s1 = red[2][tid] + red[3][tid];
            float s2 = red[4][tid] + red[5][tid];
            float s3 = red[6][tid] + red[7][tid];
            float s4 = red[8][tid] + red[9][tid];
            float s5 = red[10][tid] + red[11][tid];
            float s6 = red[12][tid] + red[13][tid];
            float s7 = red[14][tid] + red[15][tid];
            float v = ((s0 + s1) + (s2 + s3)) + ((s4 + s5) + (s6 + s7));
            v = fmaxf(v, 0.0f);

            // finish step t-1: exact normalization of vprev
            float inv = rsqrtf(fmaxf((wsum[0] + wsum[1]) + (wsum[2] + wsum[3]), 1e-24f));
            if (t > 0)
                out[((size_t)b * TT + (t - 1)) * DD + tid] = vprev * inv;

            // carry v forward; scale by stale inv purely for range control
            s_sm[tid] = (t > 0) ? v * inv : v;
            vprev = v;
        }
#pragma unroll
        for (int ii = 0; ii < 8; ii++) cur[ii] = nxt[ii];
        __syncthreads();                 // BAR_A (next step)
    }

    // drain: emit out[TT-1]
    float sq = vprev * vprev;
#pragma unroll
    for (int o = 16; o; o >>= 1) sq += __shfl_xor_sync(0xffffffffu, sq, o);
    if (tid < DD && (tid & 31) == 0) wsum[c] = sq;
    __syncthreads();
    if (tid < DD) {
        float inv = rsqrtf(fmaxf((wsum[0] + wsum[1]) + (wsum[2] + wsum[3]), 1e-24f));
        out[((size_t)b * TT + (TT - 1)) * DD + tid] = vprev * inv;
    }
}

// ---------------------------------------------------------------------------
extern "C" void kernel_launch(void* const* d_in, const int* in_sizes, int n_in,
                              void* d_out, int out_size)
{
    const float* actions = (const float*)d_in[0];
    const float* init_s  = (const float*)d_in[1];
    const float* w1      = (const float*)d_in[2];
    const float* b1      = (const float*)d_in[3];
    const float* w2      = (const float*)d_in[4];
    const float* b2      = (const float*)d_in[5];
    float* out = (float*)d_out;

    cudaFuncSetAttribute(gemm6_kernel, cudaFuncAttributeMaxDynamicSharedMemorySize,
                         NSTG * STAGE_BYTES);

    mlp1_kernel<<<MM / 8, 256>>>(actions, w1, b1);
    bprep_kernel<<<dim3(NN / 32, KK / 32), dim3(32, 8)>>>(w2);
    gemm6_kernel<<<dim3(NN / BNG, MM / BMG), 256, NSTG * STAGE_BYTES>>>(b2);
    scan_kernel<<<BB, 512>>>(init_s, out);
}

// round 8
// speedup vs baseline: 1.5231x; 1.0063x over previous
#include <cuda_runtime.h>
#include <cuda_bf16.h>
#include <math.h>
#include <stdint.h>

// Shapes (fixed)
#define BB 32
#define TT 512
#define AA 64
#define DD 128
#define HH 256
#define MM (BB*TT)     // 16384
#define NN (DD*DD)     // 16384
#define KK HH          // 256
#define KSPLIT 768     // 3*KK : A=[hi|hi|lo], B=[hi|lo|hi]

// Device scratch (allocation-free rule)
__device__ __align__(128) __nv_bfloat16 g_A2[(size_t)MM * KSPLIT];   // 25 MB
__device__ __align__(128) __nv_bfloat16 g_B2T[(size_t)NN * KSPLIT];  // 25 MB
__device__ __align__(128) float g_trans[(size_t)MM * NN];            // 1.07 GB

// ---------------------------------------------------------------------------
// PTX helpers (sm_80-class only — harness ptxas targets base sm_103)
// ---------------------------------------------------------------------------
__device__ __forceinline__ uint32_t smem_u32(const void* p) {
    uint32_t a;
    asm("{ .reg .u64 t; cvta.to.shared.u64 t, %1; cvt.u32.u64 %0, t; }" : "=r"(a) : "l"(p));
    return a;
}
__device__ __forceinline__ void cp16(uint32_t dst, const void* src) {
    asm volatile("cp.async.cg.shared.global [%0], [%1], 16;" :: "r"(dst), "l"(src) : "memory");
}
__device__ __forceinline__ void cp_commit() {
    asm volatile("cp.async.commit_group;" ::: "memory");
}
template <int N>
__device__ __forceinline__ void cp_wait() {
    asm volatile("cp.async.wait_group %0;" :: "n"(N) : "memory");
}
__device__ __forceinline__ void ldsm4(uint32_t* r, uint32_t addr) {
    asm volatile("ldmatrix.sync.aligned.m8n8.x4.shared.b16 {%0,%1,%2,%3}, [%4];"
                 : "=r"(r[0]), "=r"(r[1]), "=r"(r[2]), "=r"(r[3]) : "r"(addr));
}
__device__ __forceinline__ void mma_bf16(float* d, const uint32_t* a, const uint32_t* b) {
    asm volatile(
        "mma.sync.aligned.m16n8k16.row.col.f32.bf16.bf16.f32 "
        "{%0,%1,%2,%3}, {%4,%5,%6,%7}, {%8,%9}, {%0,%1,%2,%3};"
        : "+f"(d[0]), "+f"(d[1]), "+f"(d[2]), "+f"(d[3])
        : "r"(a[0]), "r"(a[1]), "r"(a[2]), "r"(a[3]), "r"(b[0]), "r"(b[1]));
}
// SW128 swizzle, closed form for row*128+kb (kb < 128)
__device__ __forceinline__ uint32_t swoff(uint32_t row, uint32_t kb) {
    return row * 128u + (kb ^ ((row & 7u) << 4));
}

// ---------------------------------------------------------------------------
// Kernel 1: h = relu(actions@w1+b1); write A2 = [hi | hi | lo] bf16 rows
// ---------------------------------------------------------------------------
__global__ __launch_bounds__(256) void mlp1_kernel(const float* __restrict__ actions,
                                                   const float* __restrict__ w1,
                                                   const float* __restrict__ b1)
{
    __shared__ float as[8][AA];
    const int tid = threadIdx.x;
    const int m0 = blockIdx.x * 8;

    for (int i = tid; i < 8 * AA; i += 256)
        as[i >> 6][i & 63] = actions[(size_t)m0 * AA + i];
    __syncthreads();

    const int n = tid;
    float bv = b1[n];
    float acc[8];
#pragma unroll
    for (int r = 0; r < 8; r++) acc[r] = bv;
#pragma unroll 8
    for (int a = 0; a < AA; a++) {
        float w = w1[(size_t)a * HH + n];
#pragma unroll
        for (int r = 0; r < 8; r++) acc[r] = fmaf(as[r][a], w, acc[r]);
    }
#pragma unroll
    for (int r = 0; r < 8; r++) {
        float v = fmaxf(acc[r], 0.0f);
        __nv_bfloat16 hi = __float2bfloat16_rn(v);
        __nv_bfloat16 lo = __float2bfloat16_rn(v - __bfloat162float(hi));
        size_t row = (size_t)(m0 + r) * KSPLIT;
        g_A2[row + n] = hi;
        g_A2[row + KK + n] = hi;
        g_A2[row + 2 * KK + n] = lo;
    }
}

// ---------------------------------------------------------------------------
// Kernel 1b: B2T[n, :] = [hi(w2[:,n]) | lo(w2[:,n]) | hi(w2[:,n])]  (transpose)
// ---------------------------------------------------------------------------
__global__ __launch_bounds__(256) void bprep_kernel(const float* __restrict__ w2)
{
    __shared__ float tile[32][33];
    const int tx = threadIdx.x;          // 0..31
    const int ty = threadIdx.y;          // 0..7
    const int n0 = blockIdx.x * 32;
    const int k0 = blockIdx.y * 32;
#pragma unroll
    for (int i = 0; i < 4; i++) {
        int k = k0 + ty + i * 8;
        tile[ty + i * 8][tx] = w2[(size_t)k * NN + n0 + tx];
    }
    __syncthreads();
#pragma unroll
    for (int i = 0; i < 4; i++) {
        int nrow = ty + i * 8;
        float v = tile[tx][nrow];        // w2[k0+tx, n0+nrow]
        __nv_bfloat16 hi = __float2bfloat16_rn(v);
        __nv_bfloat16 lo = __float2bfloat16_rn(v - __bfloat162float(hi));
        size_t row = (size_t)(n0 + nrow) * KSPLIT + k0 + tx;
        g_B2T[row] = hi;
        g_B2T[row + KK] = lo;
        g_B2T[row + 2 * KK] = hi;
    }
}

// ---------------------------------------------------------------------------
// Kernel 2: bf16 mma.sync GEMM  trans = A2 @ B2T^T + b2
// BM=128, BN=128, BK=64 (SW128), 3-stage cp.async, 256 threads = 8 warps,
// 2 CTAs/SM. Single barrier per k-tile: wait -> sync -> load(kt+2) -> compute.
// Safe because the sync at iter kt proves all warps finished tile kt-1, whose
// stage (kt+2)%3 is the one being overwritten.
// ---------------------------------------------------------------------------
#define BMG 128
#define BNG 128
#define BKG 64
#define NKT (KSPLIT/BKG)     // 12
#define NSTG 3
#define A_BYTES (BMG*128)    // 16384
#define B_BYTES (BNG*128)    // 16384
#define STAGE_BYTES (A_BYTES + B_BYTES)  // 32768

__global__ __launch_bounds__(256, 2) void gemm7_kernel(const float* __restrict__ bias)
{
    extern __shared__ char dsm[];
    __shared__ float bias_s[BNG];

    const uint32_t dyn = smem_u32(dsm);
    const int tid = threadIdx.x;
    const int wid = tid >> 5;
    const int lane = tid & 31;
    const int m0 = blockIdx.y * BMG;
    const int n0 = blockIdx.x * BNG;

    if (tid < BNG) bias_s[tid] = bias[n0 + tid];

    const char* Abase = (const char*)g_A2;
    const char* Bbase = (const char*)g_B2T;

    auto load_stage = [&](int s, int kt) {
        uint32_t sb = dyn + s * STAGE_BYTES;
        size_t kbyte = (size_t)kt * (BKG * 2);   // 128 B per k-tile
#pragma unroll
        for (int i = 0; i < 4; i++) {            // A: 1024 chunks of 16B
            int q = i * 256 + tid;
            uint32_t r = q >> 3, c = (q & 7) * 16;
            cp16(sb + swoff(r, c),
                 Abase + (size_t)(m0 + r) * (KSPLIT * 2) + kbyte + c);
        }
#pragma unroll
        for (int i = 0; i < 4; i++) {            // B: 1024 chunks
            int q = i * 256 + tid;
            uint32_t r = q >> 3, c = (q & 7) * 16;
            cp16(sb + A_BYTES + swoff(r, c),
                 Bbase + (size_t)(n0 + r) * (KSPLIT * 2) + kbyte + c);
        }
        cp_commit();
    };

    // prologue: 2 stages in flight
    load_stage(0, 0);
    load_stage(1, 1);

    // warp tiling: 2 (m) x 4 (n) warps, each 64x32
    const int m_w = (wid >> 2) * 64;
    const int n_w = (wid & 3) * 32;

    const uint32_t a_row = m_w + (lane & 7) + (lane & 8);          // + mi*16
    const uint32_t a_kb  = (lane >> 4) << 4;                       // + ks*32
    const uint32_t b_row = n_w + (lane & 7) + ((lane >> 4) << 3);  // + nj*16
    const uint32_t b_kb  = (lane & 8) << 1;                        // + ks*32

    float acc[4][4][4];
#pragma unroll
    for (int mi = 0; mi < 4; mi++)
#pragma unroll
        for (int nt = 0; nt < 4; nt++)
#pragma unroll
            for (int e = 0; e < 4; e++) acc[mi][nt][e] = 0.0f;

#pragma unroll 1
    for (int kt = 0; kt < NKT; kt++) {
        const int s = kt % NSTG;

        if (kt + 1 < NKT) cp_wait<1>();   // tile kt fully landed
        else              cp_wait<0>();
        __syncthreads();                  // single barrier per tile

        if (kt + 2 < NKT) load_stage((kt + 2) % NSTG, kt + 2);

        const uint32_t abase = dyn + s * STAGE_BYTES;
        const uint32_t bbase = abase + A_BYTES;

#pragma unroll
        for (int ks = 0; ks < 4; ks++) {
            uint32_t af[4][4], bf[2][4];
#pragma unroll
            for (int mi = 0; mi < 4; mi++)
                ldsm4(af[mi], abase + swoff(a_row + mi * 16, a_kb + ks * 32));
#pragma unroll
            for (int nj = 0; nj < 2; nj++)
                ldsm4(bf[nj], bbase + swoff(b_row + nj * 16, b_kb + ks * 32));
#pragma unroll
            for (int mi = 0; mi < 4; mi++)
#pragma unroll
                for (int nj = 0; nj < 2; nj++) {
                    mma_bf16(acc[mi][2 * nj],     af[mi], &bf[nj][0]);
                    mma_bf16(acc[mi][2 * nj + 1], af[mi], &bf[nj][2]);
                }
        }
    }

    // epilogue: direct float2 stores with bias
    const int cl = 2 * (lane & 3);
    const int rl = lane >> 2;
#pragma unroll
    for (int mi = 0; mi < 4; mi++) {
        int row0 = m0 + m_w + mi * 16 + rl;
#pragma unroll
        for (int nt = 0; nt < 4; nt++) {
            int lc = n_w + nt * 8 + cl;
            int col = n0 + lc;
            float bx = bias_s[lc], by = bias_s[lc + 1];
            float2 v0 = {acc[mi][nt][0] + bx, acc[mi][nt][1] + by};
            float2 v1 = {acc[mi][nt][2] + bx, acc[mi][nt][3] + by};
            *(float2*)(g_trans + (size_t)row0 * NN + col) = v0;
            *(float2*)(g_trans + (size_t)(row0 + 8) * NN + col) = v1;
        }
    }
}

// ---------------------------------------------------------------------------
// Kernel 3: scan. Double-buffered state s_nx[2][128]; warps 12-15 compute the
// previous state's squared norm during phase 1 (overlapping matvec); phase 2
// normalizes exactly and emits out[t-1]. 2 barriers/step.
// ---------------------------------------------------------------------------
__global__ __launch_bounds__(512, 1) void scan_kernel(const float* __restrict__ init_s,
                                                      float* __restrict__ out)
{
    __shared__ float s_nx[2][DD];
    __shared__ float red[16][DD];
    __shared__ float wsum[4];

    const int tid = threadIdx.x;
    const int wid = tid >> 5;
    const int lane = tid & 31;
    const int b = blockIdx.x;
    const int c = tid >> 5;              // 0..15 : 8-row chunk
    const int j = (tid & 31) * 4;        // 4-col group
    const float* Tb = g_trans + (size_t)b * TT * (DD * DD);

    // initial state in buffer 1 (read buffer of t=0); scale-invariant, raw.
    if (tid < DD) s_nx[1][tid] = init_s[tid];

    // prefetch T(0) into registers
    float4 cur[8];
#pragma unroll
    for (int ii = 0; ii < 8; ii++)
        cur[ii] = *(const float4*)(Tb + (size_t)(c * 8 + ii) * DD + j);
    __syncthreads();                     // BAR_A (t=0)

    for (int t = 0; t < TT; t++) {
        const int rb = (t & 1) ^ 1;      // read buffer (state for this matvec)
        const int wb = t & 1;            // write buffer (new state)

        // register prefetch T(t+1)
        float4 nxt[8];
        if (t + 1 < TT) {
            const float* Tn = Tb + (size_t)(t + 1) * (DD * DD);
#pragma unroll
            for (int ii = 0; ii < 8; ii++)
                nxt[ii] = *(const float4*)(Tn + (size_t)(c * 8 + ii) * DD + j);
        }

        // matvec partial: p_j += s_i * T[i][j] over this thread's 8 rows
        float4 p = {0.0f, 0.0f, 0.0f, 0.0f};
#pragma unroll
        for (int ii = 0; ii < 8; ii++) {
            float sv = s_nx[rb][c * 8 + ii];
            p.x = fmaf(sv, cur[ii].x, p.x);
            p.y = fmaf(sv, cur[ii].y, p.y);
            p.z = fmaf(sv, cur[ii].z, p.z);
            p.w = fmaf(sv, cur[ii].w, p.w);
        }
        *(float4*)&red[c][j] = p;

        // warps 12-15: squared norm of current state (for exact normalization)
        if (wid >= 12) {
            const int k = wid - 12;
            float sv = s_nx[rb][k * 32 + lane];
            float sq = sv * sv;
#pragma unroll
            for (int o = 16; o; o >>= 1) sq += __shfl_xor_sync(0xffffffffu, sq, o);
            if (lane == 0) wsum[k] = sq;
        }
        __syncthreads();                 // BAR_B

        if (tid < DD) {
            // balanced tree over 16 partial rows
            float s0 = red[0][tid] + red[1][tid];
            float s1 = red[2][tid] + red[3][tid];
            float s2 = red[4][tid] + red[5][tid];
            float s3 = red[6][tid] + red[7][tid];
            float s4 = red[8][tid] + red[9][tid];
            float s5 = red[10][tid] + red[11][tid];
            float s6 = red[12][tid] + red[13][tid];
            float s7 = red[14][tid] + red[15][tid];
            float v = ((s0 + s1) + (s2 + s3)) + ((s4 + s5) + (s6 + s7));
            v = fmaxf(v, 0.0f);

            float inv = rsqrtf(fmaxf((wsum[0] + wsum[1]) + (wsum[2] + wsum[3]), 1e-24f));
            // finish step t-1: exact normalization of prior state
            if (t > 0)
                out[((size_t)b * TT + (t - 1)) * DD + tid] = s_nx[rb][tid] * inv;
            // carry v forward, scaled by inv for range control (any positive
            // scale is exact — recurrence is positively homogeneous)
            s_nx[wb][tid] = v * inv;
        }
#pragma unroll
        for (int ii = 0; ii < 8; ii++) cur[ii] = nxt[ii];
        __syncthreads();                 // BAR_A (next step)
    }

    // drain: out[TT-1] from s_nx[(TT-1)&1]
    const int fb = (TT - 1) & 1;
    if (wid >= 12) {
        const int k = wid - 12;
        float sv = s_nx[fb][k * 32 + lane];
        float sq = sv * sv;
#pragma unroll
        for (int o = 16; o; o >>= 1) sq += __shfl_xor_sync(0xffffffffu, sq, o);
        if (lane == 0) wsum[k] = sq;
    }
    __syncthreads();
    if (tid < DD) {
        float inv = rsqrtf(fmaxf((wsum[0] + wsum[1]) + (wsum[2] + wsum[3]), 1e-24f));
        out[((size_t)b * TT + (TT - 1)) * DD + tid] = s_nx[fb][tid] * inv;
    }
}

// ---------------------------------------------------------------------------
extern "C" void kernel_launch(void* const* d_in, const int* in_sizes, int n_in,
                              void* d_out, int out_size)
{
    const float* actions = (const float*)d_in[0];
    const float* init_s  = (const float*)d_in[1];
    const float* w1      = (const float*)d_in[2];
    const float* b1      = (const float*)d_in[3];
    const float* w2      = (const float*)d_in[4];
    const float* b2      = (const float*)d_in[5];
    float* out = (float*)d_out;

    cudaFuncSetAttribute(gemm7_kernel, cudaFuncAttributeMaxDynamicSharedMemorySize,
                         NSTG * STAGE_BYTES);

    mlp1_kernel<<<MM / 8, 256>>>(actions, w1, b1);
    bprep_kernel<<<dim3(NN / 32, KK / 32), dim3(32, 8)>>>(w2);
    gemm7_kernel<<<dim3(NN / BNG, MM / BMG), 256, NSTG * STAGE_BYTES>>>(b2);
    scan_kernel<<<BB, 512>>>(init_s, out);
}